// round 4
// baseline (speedup 1.0000x reference)
#include <cuda_runtime.h>
#include <cstdint>

// HyperConnections, round 3: persistent CTAs + depth-2 cp.async token pipeline.
// Identity: dot(norm_h, w) = rstd*(sum h*g*w - mu*sum g*w) + sum beta_ln*w
// g_W / g_S1 / g_S2 token-independent, precomputed per launch.

constexpr int DIMC  = 2048;
constexpr int RATEC = 4;
constexpr int NW    = 5;           // alpha cols 1..4 (col 0 unused) + beta_fn
constexpr int TPB   = 256;
constexpr int VEC   = DIMC / TPB;  // 8
constexpr int GRID  = 304;         // 2 CTAs x 152 SMs, fully resident
constexpr float DSCALE = 0.01f;
constexpr float EPSF   = 1e-5f;

constexpr int TOKF   = RATEC * DIMC + DIMC;      // 10240 floats: h then h_o
constexpr int SMEMF  = 2 * TOKF + 8 * 28 + 28;   // + reduction scratch
constexpr int SMEMB  = SMEMF * 4;                // 82928 bytes

__device__ float g_W[NW][DIMC];
__device__ float g_S1[NW];
__device__ float g_S2[NW];

__device__ __forceinline__ void cp_async16(uint32_t saddr, const void* gptr) {
    asm volatile("cp.async.cg.shared.global [%0], [%1], 16;"
                 :: "r"(saddr), "l"(gptr));
}

__global__ void precompute_k(const float* __restrict__ gamma,
                             const float* __restrict__ lbeta,
                             const float* __restrict__ afn,   // (DIM,5)
                             const float* __restrict__ bfn) {
    const int tid = threadIdx.x;   // 512
    float s1[NW], s2[NW];
#pragma unroll
    for (int j = 0; j < NW; j++) { s1[j] = 0.f; s2[j] = 0.f; }
    for (int d = tid; d < DIMC; d += 512) {
        const float g = gamma[d], b = lbeta[d];
#pragma unroll
        for (int j = 0; j < NW; j++) {
            const float w = (j < 4) ? afn[d * 5 + j + 1] : bfn[d];
            g_W[j][d] = g * w;
            s1[j] += g * w;
            s2[j] += b * w;
        }
    }
#pragma unroll
    for (int j = 0; j < NW; j++) {
#pragma unroll
        for (int o = 16; o; o >>= 1) {
            s1[j] += __shfl_xor_sync(0xffffffffu, s1[j], o);
            s2[j] += __shfl_xor_sync(0xffffffffu, s2[j], o);
        }
    }
    __shared__ float sm[16][2 * NW];
    const int w = tid >> 5, lane = tid & 31;
    if (lane == 0) {
#pragma unroll
        for (int j = 0; j < NW; j++) { sm[w][j] = s1[j]; sm[w][NW + j] = s2[j]; }
    }
    __syncthreads();
    if (tid < 2 * NW) {
        float s = 0.f;
#pragma unroll
        for (int ww = 0; ww < 16; ww++) s += sm[ww][tid];
        if (tid < NW) g_S1[tid] = s;
        else          g_S2[tid - NW] = s;
    }
}

__device__ __forceinline__ void prefetch_token(float* buf, const float* __restrict__ h,
                                               const float* __restrict__ h_o,
                                               int t, int tid) {
    const uint32_t sb = (uint32_t)__cvta_generic_to_shared(buf);
    const float4* hs = (const float4*)(h + (size_t)t * (RATEC * DIMC));
#pragma unroll
    for (int k = 0; k < 8; k++) {                 // 2048 float4 of h
        const int idx = tid + k * TPB;
        cp_async16(sb + idx * 16, hs + idx);
    }
    const uint32_t so = sb + RATEC * DIMC * 4;
    const float4* os = (const float4*)(h_o + (size_t)t * DIMC);
#pragma unroll
    for (int k = 0; k < 2; k++) {                 // 512 float4 of h_o
        const int idx = tid + k * TPB;
        cp_async16(so + idx * 16, os + idx);
    }
    asm volatile("cp.async.commit_group;" ::: "memory");
}

__global__ __launch_bounds__(TPB, 2) void hyper_k(
    const float* __restrict__ h,    // (NTOK, RATE, DIM)
    const float* __restrict__ h_o,  // (NTOK, DIM)
    const float* __restrict__ sA,   // (RATE, 5)
    const float* __restrict__ sB,   // (RATE,)
    float* __restrict__ out,        // (NTOK, RATE, DIM)
    int ntok)
{
    extern __shared__ float smem[];
    float* buf0   = smem;
    float* buf1   = smem + TOKF;
    float* s_part = smem + 2 * TOKF;        // [8][28]
    float* s_fin  = s_part + 8 * 28;        // [28]

    const int tid = threadIdx.x;
    const int d0  = tid * VEC;
    const int w   = tid >> 5, lane = tid & 31;
    const float invD = 1.0f / DIMC;

    int t = blockIdx.x;
    if (t < ntok) prefetch_token(buf0, h, h_o, t, tid);

    int k = 0;
    for (; t < ntok; t += GRID, ++k) {
        float* cur = (k & 1) ? buf1 : buf0;
        float* nxt = (k & 1) ? buf0 : buf1;
        const int tn = t + GRID;
        if (tn < ntok) {
            prefetch_token(nxt, h, h_o, tn, tid);   // fire-and-forget
            asm volatile("cp.async.wait_group 1;" ::: "memory");
        } else {
            asm volatile("cp.async.wait_group 0;" ::: "memory");
        }
        __syncthreads();   // cur fully landed & visible

        // ---- stats + dots, h held in registers ----
        float hreg[RATEC][VEC];
        float acc[RATEC][7];
#pragma unroll
        for (int n = 0; n < RATEC; n++) {
            const float4* sp = (const float4*)(cur + n * DIMC + d0);
            const float4 a = sp[0], b = sp[1];
            hreg[n][0]=a.x; hreg[n][1]=a.y; hreg[n][2]=a.z; hreg[n][3]=a.w;
            hreg[n][4]=b.x; hreg[n][5]=b.y; hreg[n][6]=b.z; hreg[n][7]=b.w;
            float sh = 0.f, sh2 = 0.f;
#pragma unroll
            for (int i = 0; i < VEC; i++) {
                sh += hreg[n][i];
                sh2 = fmaf(hreg[n][i], hreg[n][i], sh2);
            }
            acc[n][0] = sh; acc[n][1] = sh2;
        }
#pragma unroll
        for (int j = 0; j < NW; j++) {
            const float4* wp = (const float4*)(&g_W[j][d0]);   // L1-hot
            const float4 a = wp[0], b = wp[1];
            const float wv[VEC] = {a.x,a.y,a.z,a.w,b.x,b.y,b.z,b.w};
#pragma unroll
            for (int n = 0; n < RATEC; n++) {
                float s = 0.f;
#pragma unroll
                for (int i = 0; i < VEC; i++) s = fmaf(hreg[n][i], wv[i], s);
                acc[n][2 + j] = s;
            }
        }

        // ---- 28-value block reduction ----
        float* pf = &acc[0][0];
#pragma unroll
        for (int v = 0; v < 28; v++) {
#pragma unroll
            for (int o = 16; o; o >>= 1)
                pf[v] += __shfl_xor_sync(0xffffffffu, pf[v], o);
        }
        if (lane == 0) {
#pragma unroll
            for (int v = 0; v < 28; v++) s_part[w * 28 + v] = pf[v];
        }
        __syncthreads();
        if (tid < 28) {
            float s = 0.f;
#pragma unroll
            for (int ww = 0; ww < 8; ww++) s += s_part[ww * 28 + tid];
            s_fin[tid] = s;
        }
        __syncthreads();

        // ---- alpha / beta ----
        float alpha[RATEC][RATEC];   // alpha[m][n] = full_alpha[m][n+1]
        float beta[RATEC];
#pragma unroll
        for (int m = 0; m < RATEC; m++) {
            const float mu   = s_fin[m * 7 + 0] * invD;
            const float var  = s_fin[m * 7 + 1] * invD - mu * mu;
            const float rstd = rsqrtf(var + EPSF);
#pragma unroll
            for (int j = 0; j < NW; j++) {
                const float dot = rstd * (s_fin[m * 7 + 2 + j] - mu * g_S1[j]) + g_S2[j];
                const float dyn = dot * DSCALE;
                if (j < 4) alpha[m][j] = dyn + sA[m * 5 + j + 1];
                else       beta[m]     = dyn + sB[m];
            }
        }

        // ---- mix + depth connection; stores fire-and-forget ----
        const float4* hop = (const float4*)(cur + RATEC * DIMC + d0);
        const float4 o0 = hop[0], o1 = hop[1];
        const float hov[VEC] = {o0.x,o0.y,o0.z,o0.w,o1.x,o1.y,o1.z,o1.w};
        float* ob = out + (size_t)t * (RATEC * DIMC) + d0;
#pragma unroll
        for (int n = 0; n < RATEC; n++) {
            float ov[VEC];
#pragma unroll
            for (int i = 0; i < VEC; i++) {
                float a2 = hov[i] * beta[n];
#pragma unroll
                for (int m = 0; m < RATEC; m++)
                    a2 = fmaf(alpha[m][n], hreg[m][i], a2);
                ov[i] = a2;
            }
            float4* dst = (float4*)(ob + n * DIMC);
            dst[0] = make_float4(ov[0], ov[1], ov[2], ov[3]);
            dst[1] = make_float4(ov[4], ov[5], ov[6], ov[7]);
        }

        __syncthreads();   // all reads of cur done before it is refilled next iter
    }
}

extern "C" void kernel_launch(void* const* d_in, const int* in_sizes, int n_in,
                              void* d_out, int out_size) {
    const float* h     = (const float*)d_in[0];
    const float* h_o   = (const float*)d_in[1];
    const float* gamma = (const float*)d_in[2];
    const float* lbeta = (const float*)d_in[3];
    const float* afn   = (const float*)d_in[4];
    const float* bfn   = (const float*)d_in[5];
    const float* sA    = (const float*)d_in[6];
    const float* sB    = (const float*)d_in[7];
    float* out = (float*)d_out;

    const int ntok = in_sizes[1] / DIMC;

    cudaFuncSetAttribute(hyper_k, cudaFuncAttributeMaxDynamicSharedMemorySize, SMEMB);

    precompute_k<<<1, 512>>>(gamma, lbeta, afn, bfn);
    hyper_k<<<GRID, TPB, SMEMB>>>(h, h_o, sA, sB, out, ntok);
}

// round 6
// speedup vs baseline: 1.3684x; 1.3684x over previous
#include <cuda_runtime.h>
#include <cstdint>

// HyperConnections, round 5: issue-bound fix.
// f32x2 packed math (sm_103a), 2-level shuffle reduction, alpha/beta computed
// once and broadcast, dense-coalesced v2.u64 loads/stores. One token per CTA.
// Identity: dot(norm_h, w) = rstd*(sum h*g*w - mu*sum g*w) + sum beta_ln*w

using u64 = unsigned long long;

constexpr int DIMC  = 2048;
constexpr int RATEC = 4;
constexpr int NW    = 5;      // alpha cols 1..4 (col 0 unused by output) + beta_fn
constexpr int TPB   = 256;
constexpr float DSCALE = 0.01f;
constexpr float EPSF   = 1e-5f;

__device__ float g_W[NW][DIMC];   // gamma[d] * w_j[d]
__device__ float g_S1[NW];        // sum gamma*w
__device__ float g_S2[NW];        // sum ln_beta*w

// ---- f32x2 packed helpers (sm_10x) ----
__device__ __forceinline__ u64 f2add(u64 a, u64 b) {
    u64 r; asm("add.rn.f32x2 %0,%1,%2;" : "=l"(r) : "l"(a), "l"(b)); return r;
}
__device__ __forceinline__ u64 f2mul(u64 a, u64 b) {
    u64 r; asm("mul.rn.f32x2 %0,%1,%2;" : "=l"(r) : "l"(a), "l"(b)); return r;
}
__device__ __forceinline__ u64 f2fma(u64 a, u64 b, u64 c) {
    u64 r; asm("fma.rn.f32x2 %0,%1,%2,%3;" : "=l"(r) : "l"(a), "l"(b), "l"(c)); return r;
}
__device__ __forceinline__ float f2hadd(u64 a) {
    float lo, hi; asm("mov.b64 {%0,%1},%2;" : "=f"(lo), "=f"(hi) : "l"(a));
    return lo + hi;
}
__device__ __forceinline__ void f2unpack(u64 a, float& lo, float& hi) {
    asm("mov.b64 {%0,%1},%2;" : "=f"(lo), "=f"(hi) : "l"(a));
}
__device__ __forceinline__ u64 f2bcast(float v) {
    u64 r; asm("mov.b64 %0,{%1,%1};" : "=l"(r) : "f"(v)); return r;
}
__device__ __forceinline__ void ldg2(const float* p, u64& a, u64& b) {
    asm("ld.global.nc.v2.u64 {%0,%1},[%2];" : "=l"(a), "=l"(b) : "l"(p));
}
__device__ __forceinline__ void stg2(float* p, u64 a, u64 b) {
    asm("st.global.v2.u64 [%0],{%1,%2};" :: "l"(p), "l"(a), "l"(b));
}

__global__ void precompute_k(const float* __restrict__ gamma,
                             const float* __restrict__ lbeta,
                             const float* __restrict__ afn,   // (DIM,5)
                             const float* __restrict__ bfn) {
    const int tid = threadIdx.x;   // 512
    float s1[NW], s2[NW];
#pragma unroll
    for (int j = 0; j < NW; j++) { s1[j] = 0.f; s2[j] = 0.f; }
    for (int d = tid; d < DIMC; d += 512) {
        const float g = gamma[d], b = lbeta[d];
#pragma unroll
        for (int j = 0; j < NW; j++) {
            const float w = (j < 4) ? afn[d * 5 + j + 1] : bfn[d];
            g_W[j][d] = g * w;
            s1[j] += g * w;
            s2[j] += b * w;
        }
    }
#pragma unroll
    for (int j = 0; j < NW; j++) {
#pragma unroll
        for (int o = 16; o; o >>= 1) {
            s1[j] += __shfl_xor_sync(0xffffffffu, s1[j], o);
            s2[j] += __shfl_xor_sync(0xffffffffu, s2[j], o);
        }
    }
    __shared__ float sm[16][2 * NW];
    const int w = tid >> 5, lane = tid & 31;
    if (lane == 0) {
#pragma unroll
        for (int j = 0; j < NW; j++) { sm[w][j] = s1[j]; sm[w][NW + j] = s2[j]; }
    }
    __syncthreads();
    if (tid < 2 * NW) {
        float s = 0.f;
#pragma unroll
        for (int ww = 0; ww < 16; ww++) s += sm[ww][tid];
        if (tid < NW) g_S1[tid] = s;
        else          g_S2[tid - NW] = s;
    }
}

__global__ __launch_bounds__(TPB, 2) void hyper_k(
    const float* __restrict__ h,    // (NTOK, RATE, DIM)
    const float* __restrict__ h_o,  // (NTOK, DIM)
    const float* __restrict__ sA,   // (RATE, 5)
    const float* __restrict__ sB,   // (RATE,)
    float* __restrict__ out)        // (NTOK, RATE, DIM)
{
    __shared__ float s_rows[64][28];            // per-(warp,lane-class) partials
    __shared__ float s_fin[28];
    __shared__ __align__(16) u64 s_ab[20];      // packed {v,v}: alpha[16], beta[4]

    const int tid  = threadIdx.x;
    const int lane = tid & 31, w = tid >> 5;
    const int t    = blockIdx.x;
    const size_t hb = (size_t)t * (RATEC * DIMC);
    const int i0 = tid * 4;                     // dims [i0, i0+4)
    const int i1 = (DIMC / 2) + tid * 4;        // dims [i1, i1+4)  (dense coalescing)

    // ---- Phase 1: load h (4 streams x 4 f32x2 pairs), stats + dots ----
    u64 hr[RATEC][4];
    float r[28];                                // r[m*7 + {0:sum,1:sum2,2..6:dots}]

#pragma unroll
    for (int n = 0; n < RATEC; n++) {
        const float* base = h + hb + n * DIMC;
        ldg2(base + i0, hr[n][0], hr[n][1]);
        ldg2(base + i1, hr[n][2], hr[n][3]);
        u64 s = f2add(f2add(hr[n][0], hr[n][1]), f2add(hr[n][2], hr[n][3]));
        u64 q = f2fma(hr[n][0], hr[n][0],
                f2fma(hr[n][1], hr[n][1],
                f2fma(hr[n][2], hr[n][2],
                f2mul(hr[n][3], hr[n][3]))));
        r[n * 7 + 0] = f2hadd(s);
        r[n * 7 + 1] = f2hadd(q);
    }
#pragma unroll
    for (int j = 0; j < NW; j++) {
        u64 w0, w1, w2, w3;
        ldg2(&g_W[j][i0], w0, w1);              // L1-hot across blocks
        ldg2(&g_W[j][i1], w2, w3);
#pragma unroll
        for (int n = 0; n < RATEC; n++) {
            u64 d = f2fma(hr[n][0], w0,
                    f2fma(hr[n][1], w1,
                    f2fma(hr[n][2], w2,
                    f2mul(hr[n][3], w3))));
            r[n * 7 + 2 + j] = f2hadd(d);
        }
    }

    // ---- 2-level butterfly: lane L ends with sum over {L, L^8, L^16, L^24} ----
#pragma unroll
    for (int v = 0; v < 28; v++) r[v] += __shfl_xor_sync(0xffffffffu, r[v], 16);
#pragma unroll
    for (int v = 0; v < 28; v++) r[v] += __shfl_xor_sync(0xffffffffu, r[v], 8);

    if (lane < 8) {
        const int row = w * 8 + lane;           // 64 disjoint partial rows
#pragma unroll
        for (int k = 0; k < 7; k++)
            *(float4*)&s_rows[row][k * 4] =
                make_float4(r[k*4], r[k*4+1], r[k*4+2], r[k*4+3]);
    }
    __syncthreads();

    // ---- Warp 0: final reduce (packed), then alpha/beta once ----
    if (w == 0) {
        if (tid < 14) {
            u64 a0 = 0ull, a1 = 0ull;           // (0.f,0.f)
#pragma unroll
            for (int rr = 0; rr < 32; rr++) {
                a0 = f2add(a0, *(const u64*)&s_rows[2*rr    ][2*tid]);
                a1 = f2add(a1, *(const u64*)&s_rows[2*rr + 1][2*tid]);
            }
            float lo, hi; f2unpack(f2add(a0, a1), lo, hi);
            s_fin[2*tid] = lo; s_fin[2*tid + 1] = hi;
        }
        __syncwarp();
        if (tid < 20) {
            const int m  = (tid < 16) ? (tid >> 2) : (tid - 16);
            const int jj = (tid < 16) ? (tid & 3) : 4;
            const float invD = 1.0f / DIMC;
            const float mu   = s_fin[m * 7 + 0] * invD;
            const float var  = s_fin[m * 7 + 1] * invD - mu * mu;
            const float rstd = rsqrtf(var + EPSF);
            const float dot  = rstd * (s_fin[m * 7 + 2 + jj] - mu * g_S1[jj]) + g_S2[jj];
            const float v    = dot * DSCALE +
                               ((tid < 16) ? sA[m * 5 + jj + 1] : sB[m]);
            s_ab[tid] = f2bcast(v);             // packed broadcast {v,v}
        }
    }
    __syncthreads();

    // ---- Broadcast alpha/beta to all threads (10 LDS.128) ----
    u64 AB[20];
#pragma unroll
    for (int k = 0; k < 10; k++) {
        const ulonglong2 q = *(const ulonglong2*)&s_ab[k * 2];
        AB[2*k] = q.x; AB[2*k + 1] = q.y;
    }
    // AB[m*4+n] = alpha_full[m][n+1] packed; AB[16+n] = beta[n] packed

    // ---- Phase 2: mix + depth connection, all packed ----
    u64 ho[4];
    {
        const float* ob = h_o + (size_t)t * DIMC;
        ldg2(ob + i0, ho[0], ho[1]);
        ldg2(ob + i1, ho[2], ho[3]);
    }
#pragma unroll
    for (int n = 0; n < RATEC; n++) {
        u64 o[4];
#pragma unroll
        for (int i = 0; i < 4; i++) {
            u64 a2 = f2mul(ho[i], AB[16 + n]);
            a2 = f2fma(hr[0][i], AB[0 * 4 + n], a2);
            a2 = f2fma(hr[1][i], AB[1 * 4 + n], a2);
            a2 = f2fma(hr[2][i], AB[2 * 4 + n], a2);
            a2 = f2fma(hr[3][i], AB[3 * 4 + n], a2);
            o[i] = a2;
        }
        float* dst = out + hb + n * DIMC;
        stg2(dst + i0, o[0], o[1]);
        stg2(dst + i1, o[2], o[3]);
    }
}

extern "C" void kernel_launch(void* const* d_in, const int* in_sizes, int n_in,
                              void* d_out, int out_size) {
    const float* h     = (const float*)d_in[0];
    const float* h_o   = (const float*)d_in[1];
    const float* gamma = (const float*)d_in[2];
    const float* lbeta = (const float*)d_in[3];
    const float* afn   = (const float*)d_in[4];
    const float* bfn   = (const float*)d_in[5];
    const float* sA    = (const float*)d_in[6];
    const float* sB    = (const float*)d_in[7];
    float* out = (float*)d_out;

    const int ntok = in_sizes[1] / DIMC;   // b*l from h_o element count

    precompute_k<<<1, 512>>>(gamma, lbeta, afn, bfn);
    hyper_k<<<ntok, TPB>>>(h, h_o, sA, sB, out);
}

// round 7
// speedup vs baseline: 1.6954x; 1.2390x over previous
#include <cuda_runtime.h>
#include <cstdint>

// HyperConnections, round 7: latency-exposure fix on top of the f32x2 kernel.
// - h_o prefetched before the reduction barriers (overlaps its DRAM latency)
// - alpha/beta read per-stream in the epilogue (shrinks live registers)
// - 3 CTAs/SM via __launch_bounds__(256,3)
// Identity: dot(norm_h, w) = rstd*(sum h*g*w - mu*sum g*w) + sum beta_ln*w

using u64 = unsigned long long;

constexpr int DIMC  = 2048;
constexpr int RATEC = 4;
constexpr int NW    = 5;      // alpha cols 1..4 (col 0 unused by output) + beta_fn
constexpr int TPB   = 256;
constexpr float DSCALE = 0.01f;
constexpr float EPSF   = 1e-5f;

__device__ float g_W[NW][DIMC];   // gamma[d] * w_j[d]
__device__ float g_S1[NW];        // sum gamma*w
__device__ float g_S2[NW];        // sum ln_beta*w

// ---- f32x2 packed helpers (sm_10x) ----
__device__ __forceinline__ u64 f2add(u64 a, u64 b) {
    u64 r; asm("add.rn.f32x2 %0,%1,%2;" : "=l"(r) : "l"(a), "l"(b)); return r;
}
__device__ __forceinline__ u64 f2mul(u64 a, u64 b) {
    u64 r; asm("mul.rn.f32x2 %0,%1,%2;" : "=l"(r) : "l"(a), "l"(b)); return r;
}
__device__ __forceinline__ u64 f2fma(u64 a, u64 b, u64 c) {
    u64 r; asm("fma.rn.f32x2 %0,%1,%2,%3;" : "=l"(r) : "l"(a), "l"(b), "l"(c)); return r;
}
__device__ __forceinline__ float f2hadd(u64 a) {
    float lo, hi; asm("mov.b64 {%0,%1},%2;" : "=f"(lo), "=f"(hi) : "l"(a));
    return lo + hi;
}
__device__ __forceinline__ void f2unpack(u64 a, float& lo, float& hi) {
    asm("mov.b64 {%0,%1},%2;" : "=f"(lo), "=f"(hi) : "l"(a));
}
__device__ __forceinline__ u64 f2bcast(float v) {
    u64 r; asm("mov.b64 %0,{%1,%1};" : "=l"(r) : "f"(v)); return r;
}
__device__ __forceinline__ void ldg2(const float* p, u64& a, u64& b) {
    asm("ld.global.nc.v2.u64 {%0,%1},[%2];" : "=l"(a), "=l"(b) : "l"(p));
}
__device__ __forceinline__ void stg2(float* p, u64 a, u64 b) {
    asm("st.global.v2.u64 [%0],{%1,%2};" :: "l"(p), "l"(a), "l"(b));
}

__global__ void precompute_k(const float* __restrict__ gamma,
                             const float* __restrict__ lbeta,
                             const float* __restrict__ afn,   // (DIM,5)
                             const float* __restrict__ bfn) {
    const int tid = threadIdx.x;   // 512
    float s1[NW], s2[NW];
#pragma unroll
    for (int j = 0; j < NW; j++) { s1[j] = 0.f; s2[j] = 0.f; }
    for (int d = tid; d < DIMC; d += 512) {
        const float g = gamma[d], b = lbeta[d];
#pragma unroll
        for (int j = 0; j < NW; j++) {
            const float w = (j < 4) ? afn[d * 5 + j + 1] : bfn[d];
            g_W[j][d] = g * w;
            s1[j] += g * w;
            s2[j] += b * w;
        }
    }
#pragma unroll
    for (int j = 0; j < NW; j++) {
#pragma unroll
        for (int o = 16; o; o >>= 1) {
            s1[j] += __shfl_xor_sync(0xffffffffu, s1[j], o);
            s2[j] += __shfl_xor_sync(0xffffffffu, s2[j], o);
        }
    }
    __shared__ float sm[16][2 * NW];
    const int w = tid >> 5, lane = tid & 31;
    if (lane == 0) {
#pragma unroll
        for (int j = 0; j < NW; j++) { sm[w][j] = s1[j]; sm[w][NW + j] = s2[j]; }
    }
    __syncthreads();
    if (tid < 2 * NW) {
        float s = 0.f;
#pragma unroll
        for (int ww = 0; ww < 16; ww++) s += sm[ww][tid];
        if (tid < NW) g_S1[tid] = s;
        else          g_S2[tid - NW] = s;
    }
}

__global__ __launch_bounds__(TPB, 3) void hyper_k(
    const float* __restrict__ h,    // (NTOK, RATE, DIM)
    const float* __restrict__ h_o,  // (NTOK, DIM)
    const float* __restrict__ sA,   // (RATE, 5)
    const float* __restrict__ sB,   // (RATE,)
    float* __restrict__ out)        // (NTOK, RATE, DIM)
{
    __shared__ float s_rows[64][28];            // per-(warp,lane-class) partials
    __shared__ float s_fin[28];
    __shared__ __align__(16) u64 s_ab[RATEC * 6];  // [n*6+m]: m<4 alpha[m][n], 4=beta[n]

    const int tid  = threadIdx.x;
    const int lane = tid & 31, w = tid >> 5;
    const int t    = blockIdx.x;
    const size_t hb = (size_t)t * (RATEC * DIMC);
    const int i0 = tid * 4;                     // dims [i0, i0+4)
    const int i1 = (DIMC / 2) + tid * 4;        // dims [i1, i1+4)  (dense coalescing)

    // ---- Phase 1: load h (4 streams x 4 f32x2 pairs), stats + dots ----
    u64 hr[RATEC][4];
    float r[28];                                // r[m*7 + {0:sum,1:sum2,2..6:dots}]

#pragma unroll
    for (int n = 0; n < RATEC; n++) {
        const float* base = h + hb + n * DIMC;
        ldg2(base + i0, hr[n][0], hr[n][1]);
        ldg2(base + i1, hr[n][2], hr[n][3]);
        u64 s = f2add(f2add(hr[n][0], hr[n][1]), f2add(hr[n][2], hr[n][3]));
        u64 q = f2fma(hr[n][0], hr[n][0],
                f2fma(hr[n][1], hr[n][1],
                f2fma(hr[n][2], hr[n][2],
                f2mul(hr[n][3], hr[n][3]))));
        r[n * 7 + 0] = f2hadd(s);
        r[n * 7 + 1] = f2hadd(q);
    }
#pragma unroll
    for (int j = 0; j < NW; j++) {
        u64 w0, w1, w2, w3;
        ldg2(&g_W[j][i0], w0, w1);              // L1-hot across blocks
        ldg2(&g_W[j][i1], w2, w3);
#pragma unroll
        for (int n = 0; n < RATEC; n++) {
            u64 d = f2fma(hr[n][0], w0,
                    f2fma(hr[n][1], w1,
                    f2fma(hr[n][2], w2,
                    f2mul(hr[n][3], w3))));
            r[n * 7 + 2 + j] = f2hadd(d);
        }
    }

    // ---- 2-level butterfly: lane L ends with sum over {L, L^8, L^16, L^24} ----
#pragma unroll
    for (int v = 0; v < 28; v++) r[v] += __shfl_xor_sync(0xffffffffu, r[v], 16);
#pragma unroll
    for (int v = 0; v < 28; v++) r[v] += __shfl_xor_sync(0xffffffffu, r[v], 8);

    if (lane < 8) {
        const int row = w * 8 + lane;           // 64 disjoint partial rows
#pragma unroll
        for (int k = 0; k < 7; k++)
            *(float4*)&s_rows[row][k * 4] =
                make_float4(r[k*4], r[k*4+1], r[k*4+2], r[k*4+3]);
    }

    // ---- Prefetch h_o NOW: DRAM latency overlaps reduction + barriers ----
    u64 ho[4];
    {
        const float* ob = h_o + (size_t)t * DIMC;
        ldg2(ob + i0, ho[0], ho[1]);
        ldg2(ob + i1, ho[2], ho[3]);
    }
    __syncthreads();

    // ---- Warp 0: final reduce (packed), then alpha/beta once ----
    if (w == 0) {
        if (tid < 14) {
            u64 a0 = 0ull, a1 = 0ull;           // (0.f,0.f)
#pragma unroll
            for (int rr = 0; rr < 32; rr++) {
                a0 = f2add(a0, *(const u64*)&s_rows[2*rr    ][2*tid]);
                a1 = f2add(a1, *(const u64*)&s_rows[2*rr + 1][2*tid]);
            }
            float lo, hi; f2unpack(f2add(a0, a1), lo, hi);
            s_fin[2*tid] = lo; s_fin[2*tid + 1] = hi;
        }
        __syncwarp();
        if (tid < 20) {
            const int m  = (tid < 16) ? (tid >> 2) : (tid - 16);
            const int jj = (tid < 16) ? (tid & 3) : 4;
            const float invD = 1.0f / DIMC;
            const float mu   = s_fin[m * 7 + 0] * invD;
            const float var  = s_fin[m * 7 + 1] * invD - mu * mu;
            const float rstd = rsqrtf(var + EPSF);
            const float dot  = rstd * (s_fin[m * 7 + 2 + jj] - mu * g_S1[jj]) + g_S2[jj];
            const float v    = dot * DSCALE +
                               ((tid < 16) ? sA[m * 5 + jj + 1] : sB[m]);
            // alpha[m][n=jj] at [jj*6+m]; beta[n=m] at [m*6+4]
            if (tid < 16) s_ab[jj * 6 + m] = f2bcast(v);
            else          s_ab[m * 6 + 4]  = f2bcast(v);
        }
    }
    __syncthreads();

    // ---- Phase 2: mix + depth connection; coefficients read per-stream ----
#pragma unroll
    for (int n = 0; n < RATEC; n++) {
        const ulonglong2 q0 = *(const ulonglong2*)&s_ab[n * 6 + 0];  // alpha[0..1][n]
        const ulonglong2 q1 = *(const ulonglong2*)&s_ab[n * 6 + 2];  // alpha[2..3][n]
        const u64 bn = s_ab[n * 6 + 4];                              // beta[n]
        u64 o[4];
#pragma unroll
        for (int i = 0; i < 4; i++) {
            u64 a2 = f2mul(ho[i], bn);
            a2 = f2fma(hr[0][i], q0.x, a2);
            a2 = f2fma(hr[1][i], q0.y, a2);
            a2 = f2fma(hr[2][i], q1.x, a2);
            a2 = f2fma(hr[3][i], q1.y, a2);
            o[i] = a2;
        }
        float* dst = out + hb + n * DIMC;
        stg2(dst + i0, o[0], o[1]);
        stg2(dst + i1, o[2], o[3]);
    }
}

extern "C" void kernel_launch(void* const* d_in, const int* in_sizes, int n_in,
                              void* d_out, int out_size) {
    const float* h     = (const float*)d_in[0];
    const float* h_o   = (const float*)d_in[1];
    const float* gamma = (const float*)d_in[2];
    const float* lbeta = (const float*)d_in[3];
    const float* afn   = (const float*)d_in[4];
    const float* bfn   = (const float*)d_in[5];
    const float* sA    = (const float*)d_in[6];
    const float* sB    = (const float*)d_in[7];
    float* out = (float*)d_out;

    const int ntok = in_sizes[1] / DIMC;   // b*l from h_o element count

    precompute_k<<<1, 512>>>(gamma, lbeta, afn, bfn);
    hyper_k<<<ntok, TPB>>>(h, h_o, sA, sB, out);
}